// round 12
// baseline (speedup 1.0000x reference)
#include <cuda_runtime.h>
#include <cuda_bf16.h>
#include <math.h>
#include <stdint.h>

// ---------------- problem constants ----------------
namespace {
constexpr int Bc   = 2;
constexpr int Sc   = 1024;
constexpr int Dc   = 1024;
constexpr int NHc  = 8;
constexpr int QKc  = 512;
constexpr int Vc   = 1024;
constexpr int DQKc = 64;
constexpr int DHVc = 128;
constexpr int KB2  = 2048;   // bf16 hi|lo split row width
}

// ---------------- scratch (device globals) ---------------------------------
__device__ float g_q     [Bc*Sc*QKc];   // pre-scaled q
__device__ float g_k     [Bc*Sc*QKc];
__device__ float g_v     [Bc*Sc*Vc];
__device__ float g_og    [Bc*Sc*Vc];
__device__ float g_h     [Bc*Sc*Vc];
__device__ float g_icap  [Bc*NHc*Sc];
__device__ float g_flog  [Bc*NHc*Sc];
__device__ float g_fact  [Bc*NHc*Sc];
__device__ float g_iact  [Bc*NHc*Sc];
__device__ float g_em    [Bc*NHc*Sc];
__device__ float g_invden[Bc*NHc*Sc];

__device__ __nv_bfloat16 g_xb   [Bc*Sc*KB2];
__device__ __nv_bfloat16 g_Wb   [3072*KB2];       // [Wq;Wk;Wv;Wog]
__device__ __nv_bfloat16 g_Woutb[Dc*KB2];
__device__ __nv_bfloat16 g_houtb[Bc*Sc*KB2];

// split-K partial accumulators (max shape 2048 x 2048 fp32)
__device__ float g_pa[2048*2048];
__device__ float g_pb[2048*2048];

// ---------------- mma.sync helpers -----------------------------------------
__device__ __forceinline__ uint32_t s2u(const void* p) {
    return (uint32_t)__cvta_generic_to_shared(p);
}
__device__ __forceinline__ void cp16(uint32_t saddr, const void* g) {
    asm volatile("cp.async.cg.shared.global [%0], [%1], 16;"
                 :: "r"(saddr), "l"(g) : "memory");
}
__device__ __forceinline__ void cp_commit() {
    asm volatile("cp.async.commit_group;" ::: "memory");
}
template <int N>
__device__ __forceinline__ void cp_wait() {
    asm volatile("cp.async.wait_group %0;" :: "n"(N) : "memory");
}
__device__ __forceinline__ void ldsm_x4(uint32_t* r, uint32_t addr) {
    asm volatile("ldmatrix.sync.aligned.m8n8.x4.shared.b16 {%0,%1,%2,%3}, [%4];"
                 : "=r"(r[0]), "=r"(r[1]), "=r"(r[2]), "=r"(r[3]) : "r"(addr));
}
__device__ __forceinline__ void mma16816(float* d, const uint32_t* a, const uint32_t* b) {
    asm volatile(
        "mma.sync.aligned.m16n8k16.row.col.f32.bf16.bf16.f32 "
        "{%0,%1,%2,%3}, {%4,%5,%6,%7}, {%8,%9}, {%0,%1,%2,%3};"
        : "+f"(d[0]), "+f"(d[1]), "+f"(d[2]), "+f"(d[3])
        : "r"(a[0]), "r"(a[1]), "r"(a[2]), "r"(a[3]), "r"(b[0]), "r"(b[1]));
}

// ---------------- 128x128 bf16 mma.sync GEMM tile, chunk range [c0,c1) -----
// Global chunk space: 96 = 3 terms x 32 K-chunks of 32 bf16.
// D = Ah@Bh^T + Al@Bh^T + Ah@Bl^T (fp32), partial over the given range.
// 128 threads = 4 warps (2m x 2n), warp tile 64x64, BK=32, 3-stage pipeline.
__device__ __forceinline__ void mma_gemm_tile(
    const __nv_bfloat16* __restrict__ A,
    const __nv_bfloat16* __restrict__ B,
    float* __restrict__ C, int ldc, int c0, int c1)
{
    __shared__ __align__(128) __nv_bfloat16 sA[3][128 * 32];
    __shared__ __align__(128) __nv_bfloat16 sB[3][128 * 32];

    const int tid  = threadIdx.x;
    const int wid  = tid >> 5, lane = tid & 31;
    const int wm   = (wid & 1) * 64;
    const int wn   = (wid >> 1) * 64;

    float acc[4][8][4];
#pragma unroll
    for (int i = 0; i < 4; ++i)
#pragma unroll
        for (int j = 0; j < 8; ++j)
#pragma unroll
            for (int q = 0; q < 4; ++q) acc[i][j][q] = 0.f;

    const int lrow = tid >> 2;          // 0..31
    const int lc   = tid & 3;

    auto load_stage = [&] (int cidx, int st) {
        int term = cidx >> 5, kk = cidx & 31;
        int a_k = (term == 1 ? 1024 : 0) + kk * 32;
        int b_k = (term == 2 ? 1024 : 0) + kk * 32;
#pragma unroll
        for (int u = 0; u < 4; ++u) {
            int row = lrow + 32 * u;
            int pc  = lc ^ ((row >> 1) & 3);
            cp16(s2u(&sA[st][row * 32 + pc * 8]), A + (size_t)row * KB2 + a_k + lc * 8);
            cp16(s2u(&sB[st][row * 32 + pc * 8]), B + (size_t)row * KB2 + b_k + lc * 8);
        }
        cp_commit();
    };

    load_stage(c0, 0);
    load_stage(c0 + 1, 1);

    for (int c = c0; c < c1; ++c) {
        const int rel = c - c0;
        const int buf = rel % 3;
        if (c + 1 < c1) cp_wait<1>(); else cp_wait<0>();
        __syncthreads();
        if (c + 2 < c1) load_stage(c + 2, (rel + 2) % 3);

#pragma unroll
        for (int ks = 0; ks < 2; ++ks) {
            uint32_t af[4][4];
#pragma unroll
            for (int im = 0; im < 4; ++im) {
                int row = wm + im * 16 + (lane & 15);
                int ch  = ks * 2 + ((lane >> 4) & 1);
                int pc  = ch ^ ((row >> 1) & 3);
                ldsm_x4(af[im], s2u(&sA[buf][row * 32 + pc * 8]));
            }
            uint32_t bfr[4][4];
#pragma unroll
            for (int ib = 0; ib < 4; ++ib) {
                int row = wn + ib * 16 + (lane & 7) + ((lane >> 4) & 1) * 8;
                int ch  = ks * 2 + ((lane >> 3) & 1);
                int pc  = ch ^ ((row >> 1) & 3);
                ldsm_x4(bfr[ib], s2u(&sB[buf][row * 32 + pc * 8]));
            }
#pragma unroll
            for (int im = 0; im < 4; ++im)
#pragma unroll
                for (int in = 0; in < 8; ++in)
                    mma16816(acc[im][in], af[im], &bfr[in >> 1][(in & 1) * 2]);
        }
    }

    const int group = lane >> 2, tg = lane & 3;
#pragma unroll
    for (int im = 0; im < 4; ++im) {
        int r0 = wm + im * 16 + group;
#pragma unroll
        for (int half = 0; half < 2; ++half) {
            float* crow = C + (size_t)(r0 + half * 8) * ldc;
#pragma unroll
            for (int in = 0; in < 8; ++in) {
                float2 v = make_float2(acc[im][in][half * 2],
                                       acc[im][in][half * 2 + 1]);
                *(float2*)(crow + wn + in * 8 + tg * 2) = v;
            }
        }
    }
}

// q/k projection partial GEMM: partial[2048][1024], cols 0..511 q, 512..1023 k
__global__ __launch_bounds__(128, 2) void gemm_qk_tc()
{
    const int nt = blockIdx.x;          // 0..7
    const int m0 = blockIdx.y * 128;
    const int z  = blockIdx.z;          // split-K half
    float* part = z ? g_pb : g_pa;
    mma_gemm_tile(g_xb + (size_t)m0 * KB2,
                  g_Wb + (size_t)nt * 128 * KB2,
                  part + (size_t)m0 * 1024 + nt * 128, 1024,
                  z * 48, z * 48 + 48);
}

// v/og projection partial GEMM: partial[2048][2048], cols 0..1023 v, rest og
__global__ __launch_bounds__(128, 2) void gemm_vog_tc()
{
    const int nt = blockIdx.x;          // 0..15
    const int m0 = blockIdx.y * 128;
    const int z  = blockIdx.z;
    float* part = z ? g_pb : g_pa;
    mma_gemm_tile(g_xb + (size_t)m0 * KB2,
                  g_Wb + (size_t)(1024 + nt * 128) * KB2,
                  part + (size_t)m0 * 2048 + nt * 128, 2048,
                  z * 48, z * 48 + 48);
}

// output GEMM partial: partial[2048][1024]
__global__ __launch_bounds__(128, 2) void gemm_out_tc()
{
    const int nt = blockIdx.x;          // 0..7
    const int m0 = blockIdx.y * 128;
    const int z  = blockIdx.z;
    float* part = z ? g_pb : g_pa;
    mma_gemm_tile(g_houtb + (size_t)m0 * KB2,
                  g_Woutb + (size_t)nt * 128 * KB2,
                  part + (size_t)m0 * 1024 + nt * 128, 1024,
                  z * 48, z * 48 + 48);
}

// ---------------- split-K reduction kernels ---------------------------------
__global__ void add_qk()
{
    int lidx = blockIdx.x * 256 + threadIdx.x;      // float4 units, 524288 total
    float4 a = ((const float4*)g_pa)[lidx];
    float4 b = ((const float4*)g_pb)[lidx];
    float4 s = make_float4(a.x+b.x, a.y+b.y, a.z+b.z, a.w+b.w);
    int row = lidx >> 8, col = (lidx & 255) * 4;
    if (col < 512) {
        s.x *= 0.125f; s.y *= 0.125f; s.z *= 0.125f; s.w *= 0.125f;
        *(float4*)&g_q[row * QKc + col] = s;
    } else {
        *(float4*)&g_k[row * QKc + col - 512] = s;
    }
}
__global__ void add_vog()
{
    int lidx = blockIdx.x * 256 + threadIdx.x;      // 1048576 total
    float4 a = ((const float4*)g_pa)[lidx];
    float4 b = ((const float4*)g_pb)[lidx];
    float4 s = make_float4(a.x+b.x, a.y+b.y, a.z+b.z, a.w+b.w);
    int row = lidx >> 9, col = (lidx & 511) * 4;
    if (col < 1024) *(float4*)&g_v [row * Vc + col]        = s;
    else            *(float4*)&g_og[row * Vc + col - 1024] = s;
}
__global__ void add_out(float* __restrict__ y)
{
    int lidx = blockIdx.x * 256 + threadIdx.x;      // 524288 total
    float4 a = ((const float4*)g_pa)[lidx];
    float4 b = ((const float4*)g_pb)[lidx];
    ((float4*)y)[lidx] = make_float4(a.x+b.x, a.y+b.y, a.z+b.z, a.w+b.w);
}

// ---------------- fused fp32 -> bf16 hi/lo split ----------------------------
__device__ __forceinline__ void split2(float v, __nv_bfloat16& h, __nv_bfloat16& l) {
    h = __float2bfloat16(v);
    l = __float2bfloat16(v - __bfloat162float(h));
}
namespace {
constexpr int SEG0 =  524288;             // x     (float4 units)
constexpr int SEG1 = SEG0 + 131072;       // Wq
constexpr int SEG2 = SEG1 + 131072;       // Wk
constexpr int SEG3 = SEG2 + 262144;       // Wv
constexpr int SEG4 = SEG3 + 262144;       // Wog
constexpr int SEG5 = SEG4 + 262144;       // Wout -> total 1572864
}
__global__ void cvt_all2(const float* __restrict__ x,
                         const float* __restrict__ Wq, const float* __restrict__ Wk,
                         const float* __restrict__ Wv, const float* __restrict__ Wog,
                         const float* __restrict__ Wout)
{
    int idx = (blockIdx.x * 256 + threadIdx.x) * 2;
    const float* src; __nv_bfloat16* dst; int lidx;
    if      (idx < SEG0) { src = x;    dst = g_xb;              lidx = idx; }
    else if (idx < SEG1) { src = Wq;   dst = g_Wb;              lidx = idx - SEG0; }
    else if (idx < SEG2) { src = Wk;   dst = g_Wb +  512*KB2;   lidx = idx - SEG1; }
    else if (idx < SEG3) { src = Wv;   dst = g_Wb + 1024*KB2;   lidx = idx - SEG2; }
    else if (idx < SEG4) { src = Wog;  dst = g_Wb + 2048*KB2;   lidx = idx - SEG3; }
    else                 { src = Wout; dst = g_Woutb;           lidx = idx - SEG4; }
    int row = lidx >> 8;
    int c4  = lidx & 255;
    float4 v0 = ((const float4*)src)[lidx];
    float4 v1 = ((const float4*)src)[lidx + 1];
    float vf[8] = {v0.x, v0.y, v0.z, v0.w, v1.x, v1.y, v1.z, v1.w};
    uint32_t ph[4], pl[4];
#pragma unroll
    for (int p = 0; p < 4; ++p) {
        __nv_bfloat16 h0, l0, h1, l1;
        split2(vf[2*p],   h0, l0);
        split2(vf[2*p+1], h1, l1);
        __nv_bfloat162 hh = __halves2bfloat162(h0, h1);
        __nv_bfloat162 ll = __halves2bfloat162(l0, l1);
        ph[p] = *reinterpret_cast<uint32_t*>(&hh);
        pl[p] = *reinterpret_cast<uint32_t*>(&ll);
    }
    *(uint4*)(dst + (size_t)row * KB2 + c4 * 4)        = make_uint4(ph[0], ph[1], ph[2], ph[3]);
    *(uint4*)(dst + (size_t)row * KB2 + 1024 + c4 * 4) = make_uint4(pl[0], pl[1], pl[2], pl[3]);
}

// ---------------- gate GEMV: 4 outputs per warp -----------------------------
__global__ void gates_kernel(const float* __restrict__ x,
                             const float* __restrict__ Wi, const float* __restrict__ bi,
                             const float* __restrict__ Wf, const float* __restrict__ bf)
{
    const int wid  = blockIdx.x * 8 + (threadIdx.x >> 5);  // 0..8191
    const int lane = threadIdx.x & 31;
    const int row  = wid >> 2;
    const int g    = wid & 3;
    const float4* xr = (const float4*)(x + (size_t)row * Dc);
    const float4* wr[4];
#pragma unroll
    for (int j = 0; j < 4; ++j) {
        int o = g * 4 + j;
        const float* Wp = (o < 8) ? Wi : Wf;
        wr[j] = (const float4*)(Wp + (size_t)(o & 7) * Dc);
    }
    float acc[4] = {0.f, 0.f, 0.f, 0.f};
#pragma unroll 4
    for (int c = lane; c < Dc/4; c += 32) {
        float4 xv = __ldg(&xr[c]);
#pragma unroll
        for (int j = 0; j < 4; ++j) {
            float4 wv = __ldg(&wr[j][c]);
            acc[j] += xv.x*wv.x + xv.y*wv.y + xv.z*wv.z + xv.w*wv.w;
        }
    }
#pragma unroll
    for (int j = 0; j < 4; ++j)
#pragma unroll
        for (int off = 16; off > 0; off >>= 1)
            acc[j] += __shfl_xor_sync(0xffffffffu, acc[j], off);
    if (lane == 0) {
        int b = row >> 10, t = row & (Sc - 1);
#pragma unroll
        for (int j = 0; j < 4; ++j) {
            int o = g * 4 + j;
            int h = o & 7;
            float pre = acc[j] + ((o < 8) ? bi[h] : bf[h]);
            float cap = 15.f * tanhf(pre * (1.f/15.f));
            int idx = (b * NHc + h) * Sc + t;
            if (o >= 8) {
                float fl = (cap >= 0.f) ? -log1pf(expf(-cap))
                                        : (cap - log1pf(expf(cap)));
                g_flog[idx] = fl;
            } else {
                g_icap[idx] = cap;
            }
        }
    }
}

// ---------------- parallel max-plus scan (per (b,h)) ------------------------
__global__ __launch_bounds__(128) void scan_kernel()
{
    __shared__ float wA[4], wB[4];
    const int bh = blockIdx.x, tid = threadIdx.x;
    const int lane = tid & 31, w = tid >> 5;
    const float* fl = g_flog + bh * Sc + tid * 8;
    const float* ic = g_icap + bh * Sc + tid * 8;
    float a[8], b[8];
#pragma unroll
    for (int j = 0; j < 8; ++j) { a[j] = fl[j]; b[j] = ic[j]; }
    float A = 0.f, B = -1e30f;
#pragma unroll
    for (int j = 0; j < 8; ++j) { B = fmaxf(B + a[j], b[j]); A += a[j]; }
#pragma unroll
    for (int off = 1; off < 32; off <<= 1) {
        float A2 = __shfl_up_sync(0xffffffffu, A, off);
        float B2 = __shfl_up_sync(0xffffffffu, B, off);
        if (lane >= off) { B = fmaxf(B2 + A, B); A = A2 + A; }
    }
    if (lane == 31) { wA[w] = A; wB[w] = B; }
    __syncthreads();
    float pA = 0.f, pB = -1e30f;
    for (int ww = 0; ww < w; ++ww) { pB = fmaxf(pB + wA[ww], wB[ww]); pA += wA[ww]; }
    float eA = __shfl_up_sync(0xffffffffu, A, 1);
    float eB = __shfl_up_sync(0xffffffffu, B, 1);
    if (lane == 0) { eA = 0.f; eB = -1e30f; }
    float EB = fmaxf(pB + eA, eB);
    float EA = pA + eA;
    float m = fmaxf(EA, EB);
    const int base = bh * Sc + tid * 8;
#pragma unroll
    for (int j = 0; j < 8; ++j) {
        float mp = m;
        m = fmaxf(a[j] + mp, b[j]);
        g_fact[base + j] = expf(a[j] + mp - m);
        g_iact[base + j] = expf(b[j] - m);
        g_em  [base + j] = expf(-m);
    }
}

// ---------------- n-scan + denominator: one channel per thread -------------
__global__ __launch_bounds__(64) void nscan_kernel()
{
    __shared__ float sP[32][65];
    const int bh = blockIdx.x;
    const int b = bh >> 3, h = bh & 7;
    const int d = threadIdx.x;
    const int warp = d >> 5, lane = d & 31;
    const float* kp = g_k + (size_t)b*Sc*QKc + h*DQKc + d;
    const float* qp = g_q + (size_t)b*Sc*QKc + h*DQKc + d;
    const float* fa = g_fact + bh*Sc;
    const float* ia = g_iact + bh*Sc;
    float n = 0.f;
    for (int tile = 0; tile < Sc/32; ++tile) {
        const int t0 = tile * 32;
#pragma unroll 8
        for (int s = 0; s < 32; ++s) {
            int t = t0 + s;
            float kv = __ldg(kp + (size_t)t * QKc);
            float qv = __ldg(qp + (size_t)t * QKc);
            n = fa[t]*n + ia[t]*kv;
            sP[s][d] = qv * n;
        }
        __syncthreads();
#pragma unroll
        for (int i = 0; i < 16; ++i) {
            int tt = warp * 16 + i;
            float v = sP[tt][lane] + sP[tt][lane + 32];
#pragma unroll
            for (int off = 16; off > 0; off >>= 1)
                v += __shfl_xor_sync(0xffffffffu, v, off);
            if (lane == 0) {
                int t = t0 + tt;
                float den = fmaxf(fabsf(v), g_em[bh*Sc + t]) + 1e-6f;
                g_invden[bh*Sc + t] = 1.f / den;
            }
        }
        __syncthreads();
    }
}

// ---------------- main C-state recurrence -----------------------------------
__global__ __launch_bounds__(256) void recur_kernel()
{
    __shared__ float sK[32][64];
    __shared__ float sQ[32][64];
    __shared__ float sV[32][16];
    __shared__ float sS[3][32];
    const int vb = blockIdx.x;
    const int bh = blockIdx.y;
    const int b = bh >> 3, h = bh & 7;
    const int tid = threadIdx.x;
    const int vi = tid >> 4;
    const int dc = tid & 15;

    float C[4] = {0.f, 0.f, 0.f, 0.f};
    float4 rk[2], rq[2], rv;
    float rs = 0.f;

    auto g_load = [&] (int t0) {
#pragma unroll
        for (int u = 0; u < 2; ++u) {
            int id = tid + 256*u;
            int r = id >> 4, c = id & 15;
            int gb = (b*Sc + t0 + r) * QKc + h * DQKc + c * 4;
            rk[u] = *(const float4*)&g_k[gb];
            rq[u] = *(const float4*)&g_q[gb];
        }
        if (tid < 128) {
            int r = tid >> 2, c = tid & 3;
            rv = *(const float4*)&g_v[(b*Sc + t0 + r) * Vc + h * DHVc + vb*16 + c*4];
        } else if (tid < 224) {
            int which = (tid - 128) >> 5, s = (tid - 128) & 31;
            const float* sp = (which == 0) ? g_fact : ((which == 1) ? g_iact : g_invden);
            rs = sp[bh*Sc + t0 + s];
        }
    };
    auto s_store = [&] () {
#pragma unroll
        for (int u = 0; u < 2; ++u) {
            int id = tid + 256*u;
            int r = id >> 4, c = id & 15;
            *(float4*)&sK[r][c*4] = rk[u];
            *(float4*)&sQ[r][c*4] = rq[u];
        }
        if (tid < 128) {
            int r = tid >> 2, c = tid & 3;
            *(float4*)&sV[r][c*4] = rv;
        } else if (tid < 224) {
            sS[(tid-128)>>5][(tid-128)&31] = rs;
        }
    };

    g_load(0);
    s_store();
    __syncthreads();

    const int NT = Sc / 32;
    for (int tile = 0; tile < NT; ++tile) {
        if (tile + 1 < NT) g_load((tile + 1) * 32);
#pragma unroll 4
        for (int s = 0; s < 32; ++s) {
            float fa  = sS[0][s];
            float iv  = sS[1][s] * sV[s][vi];
            float idn = sS[2][s];
            float4 k0 = *(const float4*)&sK[s][dc*4];
            float4 q0 = *(const float4*)&sQ[s][dc*4];
            C[0] = fa*C[0] + k0.x*iv;
            C[1] = fa*C[1] + k0.y*iv;
            C[2] = fa*C[2] + k0.z*iv;
            C[3] = fa*C[3] + k0.w*iv;
            float p = q0.x*C[0] + q0.y*C[1] + q0.z*C[2] + q0.w*C[3];
            p += __shfl_xor_sync(0xffffffffu, p, 1);
            p += __shfl_xor_sync(0xffffffffu, p, 2);
            p += __shfl_xor_sync(0xffffffffu, p, 4);
            p += __shfl_xor_sync(0xffffffffu, p, 8);
            if (dc == 0) {
                int t = tile*32 + s;
                g_h[(b*Sc + t) * Vc + h*DHVc + vb*16 + vi] = p * idn;
            }
        }
        if (tile + 1 < NT) {
            __syncthreads();
            s_store();
            __syncthreads();
        }
    }
}

// ------ per-head layernorm * gamma * sigmoid(o_pre) -> bf16 hi/lo pairs ----
__global__ void ln_gate_kernel(const float* __restrict__ gamma)
{
    const int row  = blockIdx.x;
    const int hd   = threadIdx.x >> 5;
    const int lane = threadIdx.x & 31;
    const int base = row * Vc + hd * DHVc + lane * 4;
    float4 hv = *(const float4*)&g_h[base];
    float sm = hv.x + hv.y + hv.z + hv.w;
#pragma unroll
    for (int off = 16; off > 0; off >>= 1)
        sm += __shfl_xor_sync(0xffffffffu, sm, off);
    float mu = sm * (1.f/128.f);
    float dx = hv.x - mu, dy = hv.y - mu, dz = hv.z - mu, dw = hv.w - mu;
    float sq = dx*dx + dy*dy + dz*dz + dw*dw;
#pragma unroll
    for (int off = 16; off > 0; off >>= 1)
        sq += __shfl_xor_sync(0xffffffffu, sq, off);
    float rstd = rsqrtf(sq * (1.f/128.f) + 1e-6f);
    float4 gm = *(const float4*)&gamma[hd * DHVc + lane * 4];
    float4 og = *(const float4*)&g_og[base];
    float ox = dx * rstd * gm.x / (1.f + expf(-og.x));
    float oy = dy * rstd * gm.y / (1.f + expf(-og.y));
    float oz = dz * rstd * gm.z / (1.f + expf(-og.z));
    float ow = dw * rstd * gm.w / (1.f + expf(-og.w));
    __nv_bfloat16 h0,h1,h2,h3,l0,l1,l2,l3;
    split2(ox,h0,l0); split2(oy,h1,l1); split2(oz,h2,l2); split2(ow,h3,l3);
    const int col = hd * DHVc + lane * 4;
    __nv_bfloat162* dh = (__nv_bfloat162*)(g_houtb + (size_t)row * KB2 + col);
    dh[0] = __halves2bfloat162(h0, h1);
    dh[1] = __halves2bfloat162(h2, h3);
    __nv_bfloat162* dl = (__nv_bfloat162*)(g_houtb + (size_t)row * KB2 + 1024 + col);
    dl[0] = __halves2bfloat162(l0, l1);
    dl[1] = __halves2bfloat162(l2, l3);
}

// ---------------- launch ----------------------------------------------------
extern "C" void kernel_launch(void* const* d_in, const int* in_sizes, int n_in,
                              void* d_out, int out_size)
{
    const float* x     = (const float*)d_in[0];
    const float* Wq    = (const float*)d_in[1];
    const float* Wk    = (const float*)d_in[2];
    const float* Wv    = (const float*)d_in[3];
    const float* Wog   = (const float*)d_in[4];
    const float* Wi    = (const float*)d_in[5];
    const float* bi    = (const float*)d_in[6];
    const float* Wf    = (const float*)d_in[7];
    const float* bf    = (const float*)d_in[8];
    const float* gamma = (const float*)d_in[9];
    const float* Wout  = (const float*)d_in[10];
    float* y = (float*)d_out;

    cudaStream_t s2;
    cudaStreamCreateWithFlags(&s2, cudaStreamNonBlocking);
    cudaEvent_t e1, e_qk, e_ns;
    cudaEventCreateWithFlags(&e1,   cudaEventDisableTiming);
    cudaEventCreateWithFlags(&e_qk, cudaEventDisableTiming);
    cudaEventCreateWithFlags(&e_ns, cudaEventDisableTiming);

    // side stream: gates + m-scan (depend only on raw x)
    cudaEventRecord(e1, 0);
    cudaStreamWaitEvent(s2, e1, 0);
    gates_kernel<<<1024, 256, 0, s2>>>(x, Wi, bi, Wf, bf);
    scan_kernel<<<16, 128, 0, s2>>>();

    // main: conversions + q/k GEMM (split-K x2) + reduce
    cvt_all2<<<3072, 256>>>(x, Wq, Wk, Wv, Wog, Wout);
    gemm_qk_tc<<<dim3(8, 16, 2), 128>>>();
    add_qk<<<2048, 256>>>();
    cudaEventRecord(e_qk, 0);

    // side stream: nscan (needs q,k + scan outputs), overlapping v/og GEMM
    cudaStreamWaitEvent(s2, e_qk, 0);
    nscan_kernel<<<16, 64, 0, s2>>>();
    cudaEventRecord(e_ns, s2);

    // main: v/og GEMM (split-K x2) + reduce, concurrent with nscan
    gemm_vog_tc<<<dim3(16, 16, 2), 128>>>();
    add_vog<<<4096, 256>>>();

    // join: recur needs v, fact/iact/invden
    cudaStreamWaitEvent(0, e_ns, 0);
    recur_kernel<<<dim3(8, 16), 256>>>();
    ln_gate_kernel<<<Bc * Sc, 256>>>(gamma);
    gemm_out_tc<<<dim3(8, 16, 2), 128>>>();
    add_out<<<2048, 256>>>(y);

    cudaEventDestroy(e1);
    cudaEventDestroy(e_qk);
    cudaEventDestroy(e_ns);
    cudaStreamDestroy(s2);
}

// round 14
// speedup vs baseline: 1.3253x; 1.3253x over previous
#include <cuda_runtime.h>
#include <cuda_bf16.h>
#include <math.h>
#include <stdint.h>

// ---------------- problem constants ----------------
namespace {
constexpr int Bc   = 2;
constexpr int Sc   = 1024;
constexpr int Dc   = 1024;
constexpr int NHc  = 8;
constexpr int QKc  = 512;
constexpr int Vc   = 1024;
constexpr int DQKc = 64;
constexpr int DHVc = 128;
constexpr int KB2  = 2048;   // bf16 hi|lo split row width
}

// ---------------- scratch (device globals) ---------------------------------
__device__ float g_q     [Bc*Sc*QKc];   // pre-scaled q
__device__ float g_k     [Bc*Sc*QKc];
__device__ float g_v     [Bc*Sc*Vc];
__device__ float g_og    [Bc*Sc*Vc];
__device__ float g_h     [Bc*Sc*Vc];
__device__ float g_icap  [Bc*NHc*Sc];
__device__ float g_flog  [Bc*NHc*Sc];
__device__ float g_fact  [Bc*NHc*Sc];
__device__ float g_iact  [Bc*NHc*Sc];
__device__ float g_em    [Bc*NHc*Sc];
__device__ float g_invden[Bc*NHc*Sc];

__device__ __nv_bfloat16 g_xb   [Bc*Sc*KB2];
__device__ __nv_bfloat16 g_Wb   [3072*KB2];       // [Wq;Wk;Wv;Wog]
__device__ __nv_bfloat16 g_Woutb[Dc*KB2];
__device__ __nv_bfloat16 g_houtb[Bc*Sc*KB2];

// ---------------- mma.sync helpers -----------------------------------------
__device__ __forceinline__ uint32_t s2u(const void* p) {
    return (uint32_t)__cvta_generic_to_shared(p);
}
__device__ __forceinline__ void cp16(uint32_t saddr, const void* g) {
    asm volatile("cp.async.cg.shared.global [%0], [%1], 16;"
                 :: "r"(saddr), "l"(g) : "memory");
}
__device__ __forceinline__ void cp_commit() {
    asm volatile("cp.async.commit_group;" ::: "memory");
}
template <int N>
__device__ __forceinline__ void cp_wait() {
    asm volatile("cp.async.wait_group %0;" :: "n"(N) : "memory");
}
__device__ __forceinline__ void ldsm_x4(uint32_t* r, uint32_t addr) {
    asm volatile("ldmatrix.sync.aligned.m8n8.x4.shared.b16 {%0,%1,%2,%3}, [%4];"
                 : "=r"(r[0]), "=r"(r[1]), "=r"(r[2]), "=r"(r[3]) : "r"(addr));
}
__device__ __forceinline__ void mma16816(float* d, const uint32_t* a, const uint32_t* b) {
    asm volatile(
        "mma.sync.aligned.m16n8k16.row.col.f32.bf16.bf16.f32 "
        "{%0,%1,%2,%3}, {%4,%5,%6,%7}, {%8,%9}, {%0,%1,%2,%3};"
        : "+f"(d[0]), "+f"(d[1]), "+f"(d[2]), "+f"(d[3])
        : "r"(a[0]), "r"(a[1]), "r"(a[2]), "r"(a[3]), "r"(b[0]), "r"(b[1]));
}

// ---------------- 128x128 bf16 mma.sync GEMM tile, 3-term split K ----------
// 128 threads = 4 warps (2m x 2n), warp tile 64x64, BK=32, 3-stage pipeline.
// D = Ah@Bh^T + Al@Bh^T + Ah@Bl^T (fp32 accumulate).
__device__ __forceinline__ void mma_gemm_tile(
    const __nv_bfloat16* __restrict__ A,
    const __nv_bfloat16* __restrict__ B,
    float* __restrict__ C, int ldc, float scale)
{
    __shared__ __align__(128) __nv_bfloat16 sA[3][128 * 32];
    __shared__ __align__(128) __nv_bfloat16 sB[3][128 * 32];

    const int tid  = threadIdx.x;
    const int wid  = tid >> 5, lane = tid & 31;
    const int wm   = (wid & 1) * 64;
    const int wn   = (wid >> 1) * 64;

    float acc[4][8][4];
#pragma unroll
    for (int i = 0; i < 4; ++i)
#pragma unroll
        for (int j = 0; j < 8; ++j)
#pragma unroll
            for (int q = 0; q < 4; ++q) acc[i][j][q] = 0.f;

    const int lrow = tid >> 2;          // 0..31
    const int lc   = tid & 3;

    const int NCH = 96;                 // 3 terms x 32 chunks of K=32
    auto load_stage = [&] (int cidx, int st) {
        int term = cidx >> 5, kk = cidx & 31;
        int a_k = (term == 1 ? 1024 : 0) + kk * 32;
        int b_k = (term == 2 ? 1024 : 0) + kk * 32;
#pragma unroll
        for (int u = 0; u < 4; ++u) {
            int row = lrow + 32 * u;
            int pc  = lc ^ ((row >> 1) & 3);
            cp16(s2u(&sA[st][row * 32 + pc * 8]), A + (size_t)row * KB2 + a_k + lc * 8);
            cp16(s2u(&sB[st][row * 32 + pc * 8]), B + (size_t)row * KB2 + b_k + lc * 8);
        }
        cp_commit();
    };

    load_stage(0, 0);
    load_stage(1, 1);

    for (int c = 0; c < NCH; ++c) {
        const int buf = c % 3;
        if (c + 1 < NCH) cp_wait<1>(); else cp_wait<0>();
        __syncthreads();
        if (c + 2 < NCH) load_stage(c + 2, (c + 2) % 3);

#pragma unroll
        for (int ks = 0; ks < 2; ++ks) {
            uint32_t af[4][4];
#pragma unroll
            for (int im = 0; im < 4; ++im) {
                int row = wm + im * 16 + (lane & 15);
                int ch  = ks * 2 + ((lane >> 4) & 1);
                int pc  = ch ^ ((row >> 1) & 3);
                ldsm_x4(af[im], s2u(&sA[buf][row * 32 + pc * 8]));
            }
            uint32_t bfr[4][4];
#pragma unroll
            for (int ib = 0; ib < 4; ++ib) {
                int row = wn + ib * 16 + (lane & 7) + ((lane >> 4) & 1) * 8;
                int ch  = ks * 2 + ((lane >> 3) & 1);
                int pc  = ch ^ ((row >> 1) & 3);
                ldsm_x4(bfr[ib], s2u(&sB[buf][row * 32 + pc * 8]));
            }
#pragma unroll
            for (int im = 0; im < 4; ++im)
#pragma unroll
                for (int in = 0; in < 8; ++in)
                    mma16816(acc[im][in], af[im], &bfr[in >> 1][(in & 1) * 2]);
        }
    }

    const int group = lane >> 2, tg = lane & 3;
#pragma unroll
    for (int im = 0; im < 4; ++im) {
        int r0 = wm + im * 16 + group;
#pragma unroll
        for (int half = 0; half < 2; ++half) {
            float* crow = C + (size_t)(r0 + half * 8) * ldc;
#pragma unroll
            for (int in = 0; in < 8; ++in) {
                float2 v = make_float2(acc[im][in][half * 2]     * scale,
                                       acc[im][in][half * 2 + 1] * scale);
                *(float2*)(crow + wn + in * 8 + tg * 2) = v;
            }
        }
    }
}

// q/k projections (n-tiles 0..3 -> q scaled, 4..7 -> k)
__global__ __launch_bounds__(128, 2) void gemm_qk_tc()
{
    const int nt = blockIdx.x;          // 0..7
    const int m0 = blockIdx.y * 128;
    float* Cp; int n0; float scale = 1.f;
    if (nt < 4) { Cp = g_q; n0 = nt * 128;       scale = 0.125f; }
    else        { Cp = g_k; n0 = (nt - 4) * 128; }
    mma_gemm_tile(g_xb + (size_t)m0 * KB2,
                  g_Wb + (size_t)nt * 128 * KB2,
                  Cp + (size_t)m0 * QKc + n0, QKc, scale);
}

// v/og projections (n-tiles 0..7 -> v, 8..15 -> og)
__global__ __launch_bounds__(128, 2) void gemm_vog_tc()
{
    const int nt = blockIdx.x;          // 0..15
    const int m0 = blockIdx.y * 128;
    float* Cp; int n0;
    if (nt < 8) { Cp = g_v;  n0 = nt * 128; }
    else        { Cp = g_og; n0 = (nt - 8) * 128; }
    mma_gemm_tile(g_xb + (size_t)m0 * KB2,
                  g_Wb + (size_t)(1024 + nt * 128) * KB2,
                  Cp + (size_t)m0 * Vc + n0, Vc, 1.f);
}

__global__ __launch_bounds__(128, 2) void gemm_out_tc(float* __restrict__ y)
{
    const int n0 = blockIdx.x * 128;
    const int m0 = blockIdx.y * 128;
    mma_gemm_tile(g_houtb + (size_t)m0 * KB2,
                  g_Woutb + (size_t)n0 * KB2,
                  y + (size_t)m0 * Dc + n0, Dc, 1.f);
}

// ---------------- fused fp32 -> bf16 hi/lo split ----------------------------
__device__ __forceinline__ void split2(float v, __nv_bfloat16& h, __nv_bfloat16& l) {
    h = __float2bfloat16(v);
    l = __float2bfloat16(v - __bfloat162float(h));
}
namespace {
constexpr int SEG0 =  524288;             // x     (float4 units)
constexpr int SEG1 = SEG0 + 131072;       // Wq
constexpr int SEG2 = SEG1 + 131072;       // Wk
constexpr int SEG3 = SEG2 + 262144;       // Wv
constexpr int SEG4 = SEG3 + 262144;       // Wog
constexpr int SEG5 = SEG4 + 262144;       // Wout -> total 1572864
}
__global__ void cvt_all2(const float* __restrict__ x,
                         const float* __restrict__ Wq, const float* __restrict__ Wk,
                         const float* __restrict__ Wv, const float* __restrict__ Wog,
                         const float* __restrict__ Wout)
{
    int idx = (blockIdx.x * 256 + threadIdx.x) * 2;
    const float* src; __nv_bfloat16* dst; int lidx;
    if      (idx < SEG0) { src = x;    dst = g_xb;              lidx = idx; }
    else if (idx < SEG1) { src = Wq;   dst = g_Wb;              lidx = idx - SEG0; }
    else if (idx < SEG2) { src = Wk;   dst = g_Wb +  512*KB2;   lidx = idx - SEG1; }
    else if (idx < SEG3) { src = Wv;   dst = g_Wb + 1024*KB2;   lidx = idx - SEG2; }
    else if (idx < SEG4) { src = Wog;  dst = g_Wb + 2048*KB2;   lidx = idx - SEG3; }
    else                 { src = Wout; dst = g_Woutb;           lidx = idx - SEG4; }
    int row = lidx >> 8;
    int c4  = lidx & 255;
    float4 v0 = ((const float4*)src)[lidx];
    float4 v1 = ((const float4*)src)[lidx + 1];
    float vf[8] = {v0.x, v0.y, v0.z, v0.w, v1.x, v1.y, v1.z, v1.w};
    uint32_t ph[4], pl[4];
#pragma unroll
    for (int p = 0; p < 4; ++p) {
        __nv_bfloat16 h0, l0, h1, l1;
        split2(vf[2*p],   h0, l0);
        split2(vf[2*p+1], h1, l1);
        __nv_bfloat162 hh = __halves2bfloat162(h0, h1);
        __nv_bfloat162 ll = __halves2bfloat162(l0, l1);
        ph[p] = *reinterpret_cast<uint32_t*>(&hh);
        pl[p] = *reinterpret_cast<uint32_t*>(&ll);
    }
    *(uint4*)(dst + (size_t)row * KB2 + c4 * 4)        = make_uint4(ph[0], ph[1], ph[2], ph[3]);
    *(uint4*)(dst + (size_t)row * KB2 + 1024 + c4 * 4) = make_uint4(pl[0], pl[1], pl[2], pl[3]);
}

// ---------------- gate GEMV: 4 outputs per warp -----------------------------
__global__ void gates_kernel(const float* __restrict__ x,
                             const float* __restrict__ Wi, const float* __restrict__ bi,
                             const float* __restrict__ Wf, const float* __restrict__ bf)
{
    const int wid  = blockIdx.x * 8 + (threadIdx.x >> 5);  // 0..8191
    const int lane = threadIdx.x & 31;
    const int row  = wid >> 2;
    const int g    = wid & 3;
    const float4* xr = (const float4*)(x + (size_t)row * Dc);
    const float4* wr[4];
#pragma unroll
    for (int j = 0; j < 4; ++j) {
        int o = g * 4 + j;
        const float* Wp = (o < 8) ? Wi : Wf;
        wr[j] = (const float4*)(Wp + (size_t)(o & 7) * Dc);
    }
    float acc[4] = {0.f, 0.f, 0.f, 0.f};
#pragma unroll 4
    for (int c = lane; c < Dc/4; c += 32) {
        float4 xv = __ldg(&xr[c]);
#pragma unroll
        for (int j = 0; j < 4; ++j) {
            float4 wv = __ldg(&wr[j][c]);
            acc[j] += xv.x*wv.x + xv.y*wv.y + xv.z*wv.z + xv.w*wv.w;
        }
    }
#pragma unroll
    for (int j = 0; j < 4; ++j)
#pragma unroll
        for (int off = 16; off > 0; off >>= 1)
            acc[j] += __shfl_xor_sync(0xffffffffu, acc[j], off);
    if (lane == 0) {
        int b = row >> 10, t = row & (Sc - 1);
#pragma unroll
        for (int j = 0; j < 4; ++j) {
            int o = g * 4 + j;
            int h = o & 7;
            float pre = acc[j] + ((o < 8) ? bi[h] : bf[h]);
            float cap = 15.f * tanhf(pre * (1.f/15.f));
            int idx = (b * NHc + h) * Sc + t;
            if (o >= 8) {
                float fl = (cap >= 0.f) ? -log1pf(expf(-cap))
                                        : (cap - log1pf(expf(cap)));
                g_flog[idx] = fl;
            } else {
                g_icap[idx] = cap;
            }
        }
    }
}

// ---------------- parallel max-plus scan (per (b,h)) ------------------------
__global__ __launch_bounds__(128) void scan_kernel()
{
    __shared__ float wA[4], wB[4];
    const int bh = blockIdx.x, tid = threadIdx.x;
    const int lane = tid & 31, w = tid >> 5;
    const float* fl = g_flog + bh * Sc + tid * 8;
    const float* ic = g_icap + bh * Sc + tid * 8;
    float a[8], b[8];
#pragma unroll
    for (int j = 0; j < 8; ++j) { a[j] = fl[j]; b[j] = ic[j]; }
    float A = 0.f, B = -1e30f;
#pragma unroll
    for (int j = 0; j < 8; ++j) { B = fmaxf(B + a[j], b[j]); A += a[j]; }
#pragma unroll
    for (int off = 1; off < 32; off <<= 1) {
        float A2 = __shfl_up_sync(0xffffffffu, A, off);
        float B2 = __shfl_up_sync(0xffffffffu, B, off);
        if (lane >= off) { B = fmaxf(B2 + A, B); A = A2 + A; }
    }
    if (lane == 31) { wA[w] = A; wB[w] = B; }
    __syncthreads();
    float pA = 0.f, pB = -1e30f;
    for (int ww = 0; ww < w; ++ww) { pB = fmaxf(pB + wA[ww], wB[ww]); pA += wA[ww]; }
    float eA = __shfl_up_sync(0xffffffffu, A, 1);
    float eB = __shfl_up_sync(0xffffffffu, B, 1);
    if (lane == 0) { eA = 0.f; eB = -1e30f; }
    float EB = fmaxf(pB + eA, eB);
    float EA = pA + eA;
    float m = fmaxf(EA, EB);
    const int base = bh * Sc + tid * 8;
#pragma unroll
    for (int j = 0; j < 8; ++j) {
        float mp = m;
        m = fmaxf(a[j] + mp, b[j]);
        g_fact[base + j] = expf(a[j] + mp - m);
        g_iact[base + j] = expf(b[j] - m);
        g_em  [base + j] = expf(-m);
    }
}

// ---------------- n-scan + denominator: one channel per thread -------------
__global__ __launch_bounds__(64) void nscan_kernel()
{
    __shared__ float sP[32][65];
    const int bh = blockIdx.x;
    const int b = bh >> 3, h = bh & 7;
    const int d = threadIdx.x;
    const int warp = d >> 5, lane = d & 31;
    const float* kp = g_k + (size_t)b*Sc*QKc + h*DQKc + d;
    const float* qp = g_q + (size_t)b*Sc*QKc + h*DQKc + d;
    const float* fa = g_fact + bh*Sc;
    const float* ia = g_iact + bh*Sc;
    float n = 0.f;
    for (int tile = 0; tile < Sc/32; ++tile) {
        const int t0 = tile * 32;
#pragma unroll 8
        for (int s = 0; s < 32; ++s) {
            int t = t0 + s;
            float kv = __ldg(kp + (size_t)t * QKc);
            float qv = __ldg(qp + (size_t)t * QKc);
            n = fa[t]*n + ia[t]*kv;
            sP[s][d] = qv * n;
        }
        __syncthreads();
#pragma unroll
        for (int i = 0; i < 16; ++i) {
            int tt = warp * 16 + i;
            float v = sP[tt][lane] + sP[tt][lane + 32];
#pragma unroll
            for (int off = 16; off > 0; off >>= 1)
                v += __shfl_xor_sync(0xffffffffu, v, off);
            if (lane == 0) {
                int t = t0 + tt;
                float den = fmaxf(fabsf(v), g_em[bh*Sc + t]) + 1e-6f;
                g_invden[bh*Sc + t] = 1.f / den;
            }
        }
        __syncthreads();
    }
}

// ---------------- main C-state recurrence -----------------------------------
__global__ __launch_bounds__(256) void recur_kernel()
{
    __shared__ float sK[32][64];
    __shared__ float sQ[32][64];
    __shared__ float sV[32][16];
    __shared__ float sS[3][32];
    const int vb = blockIdx.x;
    const int bh = blockIdx.y;
    const int b = bh >> 3, h = bh & 7;
    const int tid = threadIdx.x;
    const int vi = tid >> 4;
    const int dc = tid & 15;

    float C[4] = {0.f, 0.f, 0.f, 0.f};
    float4 rk[2], rq[2], rv;
    float rs = 0.f;

    auto g_load = [&] (int t0) {
#pragma unroll
        for (int u = 0; u < 2; ++u) {
            int id = tid + 256*u;
            int r = id >> 4, c = id & 15;
            int gb = (b*Sc + t0 + r) * QKc + h * DQKc + c * 4;
            rk[u] = *(const float4*)&g_k[gb];
            rq[u] = *(const float4*)&g_q[gb];
        }
        if (tid < 128) {
            int r = tid >> 2, c = tid & 3;
            rv = *(const float4*)&g_v[(b*Sc + t0 + r) * Vc + h * DHVc + vb*16 + c*4];
        } else if (tid < 224) {
            int which = (tid - 128) >> 5, s = (tid - 128) & 31;
            const float* sp = (which == 0) ? g_fact : ((which == 1) ? g_iact : g_invden);
            rs = sp[bh*Sc + t0 + s];
        }
    };
    auto s_store = [&] () {
#pragma unroll
        for (int u = 0; u < 2; ++u) {
            int id = tid + 256*u;
            int r = id >> 4, c = id & 15;
            *(float4*)&sK[r][c*4] = rk[u];
            *(float4*)&sQ[r][c*4] = rq[u];
        }
        if (tid < 128) {
            int r = tid >> 2, c = tid & 3;
            *(float4*)&sV[r][c*4] = rv;
        } else if (tid < 224) {
            sS[(tid-128)>>5][(tid-128)&31] = rs;
        }
    };

    g_load(0);
    s_store();
    __syncthreads();

    const int NT = Sc / 32;
    for (int tile = 0; tile < NT; ++tile) {
        if (tile + 1 < NT) g_load((tile + 1) * 32);
#pragma unroll 4
        for (int s = 0; s < 32; ++s) {
            float fa  = sS[0][s];
            float iv  = sS[1][s] * sV[s][vi];
            float idn = sS[2][s];
            float4 k0 = *(const float4*)&sK[s][dc*4];
            float4 q0 = *(const float4*)&sQ[s][dc*4];
            C[0] = fa*C[0] + k0.x*iv;
            C[1] = fa*C[1] + k0.y*iv;
            C[2] = fa*C[2] + k0.z*iv;
            C[3] = fa*C[3] + k0.w*iv;
            float p = q0.x*C[0] + q0.y*C[1] + q0.z*C[2] + q0.w*C[3];
            p += __shfl_xor_sync(0xffffffffu, p, 1);
            p += __shfl_xor_sync(0xffffffffu, p, 2);
            p += __shfl_xor_sync(0xffffffffu, p, 4);
            p += __shfl_xor_sync(0xffffffffu, p, 8);
            if (dc == 0) {
                int t = tile*32 + s;
                g_h[(b*Sc + t) * Vc + h*DHVc + vb*16 + vi] = p * idn;
            }
        }
        if (tile + 1 < NT) {
            __syncthreads();
            s_store();
            __syncthreads();
        }
    }
}

// ------ per-head layernorm * gamma * sigmoid(o_pre) -> bf16 hi/lo pairs ----
__global__ void ln_gate_kernel(const float* __restrict__ gamma)
{
    const int row  = blockIdx.x;
    const int hd   = threadIdx.x >> 5;
    const int lane = threadIdx.x & 31;
    const int base = row * Vc + hd * DHVc + lane * 4;
    float4 hv = *(const float4*)&g_h[base];
    float sm = hv.x + hv.y + hv.z + hv.w;
#pragma unroll
    for (int off = 16; off > 0; off >>= 1)
        sm += __shfl_xor_sync(0xffffffffu, sm, off);
    float mu = sm * (1.f/128.f);
    float dx = hv.x - mu, dy = hv.y - mu, dz = hv.z - mu, dw = hv.w - mu;
    float sq = dx*dx + dy*dy + dz*dz + dw*dw;
#pragma unroll
    for (int off = 16; off > 0; off >>= 1)
        sq += __shfl_xor_sync(0xffffffffu, sq, off);
    float rstd = rsqrtf(sq * (1.f/128.f) + 1e-6f);
    float4 gm = *(const float4*)&gamma[hd * DHVc + lane * 4];
    float4 og = *(const float4*)&g_og[base];
    float ox = dx * rstd * gm.x / (1.f + expf(-og.x));
    float oy = dy * rstd * gm.y / (1.f + expf(-og.y));
    float oz = dz * rstd * gm.z / (1.f + expf(-og.z));
    float ow = dw * rstd * gm.w / (1.f + expf(-og.w));
    __nv_bfloat16 h0,h1,h2,h3,l0,l1,l2,l3;
    split2(ox,h0,l0); split2(oy,h1,l1); split2(oz,h2,l2); split2(ow,h3,l3);
    const int col = hd * DHVc + lane * 4;
    __nv_bfloat162* dh = (__nv_bfloat162*)(g_houtb + (size_t)row * KB2 + col);
    dh[0] = __halves2bfloat162(h0, h1);
    dh[1] = __halves2bfloat162(h2, h3);
    __nv_bfloat162* dl = (__nv_bfloat162*)(g_houtb + (size_t)row * KB2 + 1024 + col);
    dl[0] = __halves2bfloat162(l0, l1);
    dl[1] = __halves2bfloat162(l2, l3);
}

// ---------------- launch ----------------------------------------------------
extern "C" void kernel_launch(void* const* d_in, const int* in_sizes, int n_in,
                              void* d_out, int out_size)
{
    const float* x     = (const float*)d_in[0];
    const float* Wq    = (const float*)d_in[1];
    const float* Wk    = (const float*)d_in[2];
    const float* Wv    = (const float*)d_in[3];
    const float* Wog   = (const float*)d_in[4];
    const float* Wi    = (const float*)d_in[5];
    const float* bi    = (const float*)d_in[6];
    const float* Wf    = (const float*)d_in[7];
    const float* bf    = (const float*)d_in[8];
    const float* gamma = (const float*)d_in[9];
    const float* Wout  = (const float*)d_in[10];
    float* y = (float*)d_out;

    cudaStream_t s2, s3;
    cudaStreamCreateWithFlags(&s2, cudaStreamNonBlocking);
    cudaStreamCreateWithFlags(&s3, cudaStreamNonBlocking);
    cudaEvent_t e1, e_cvt, e_qk, e_ns, e_vog;
    cudaEventCreateWithFlags(&e1,    cudaEventDisableTiming);
    cudaEventCreateWithFlags(&e_cvt, cudaEventDisableTiming);
    cudaEventCreateWithFlags(&e_qk,  cudaEventDisableTiming);
    cudaEventCreateWithFlags(&e_ns,  cudaEventDisableTiming);
    cudaEventCreateWithFlags(&e_vog, cudaEventDisableTiming);

    // side stream s2: gates + m-scan (depend only on raw x)
    cudaEventRecord(e1, 0);
    cudaStreamWaitEvent(s2, e1, 0);
    gates_kernel<<<1024, 256, 0, s2>>>(x, Wi, bi, Wf, bf);
    scan_kernel<<<16, 128, 0, s2>>>();

    // main: conversions
    cvt_all2<<<3072, 256>>>(x, Wq, Wk, Wv, Wog, Wout);
    cudaEventRecord(e_cvt, 0);

    // main: q/k GEMM (128 CTAs); s3: v/og GEMM (256 CTAs) CONCURRENTLY
    cudaStreamWaitEvent(s3, e_cvt, 0);
    gemm_qk_tc<<<dim3(8, 16), 128>>>();
    cudaEventRecord(e_qk, 0);
    gemm_vog_tc<<<dim3(16, 16), 128, 0, s3>>>();
    cudaEventRecord(e_vog, s3);

    // side stream s2: nscan (needs q,k + scan outputs), overlapping vog tail
    cudaStreamWaitEvent(s2, e_qk, 0);
    nscan_kernel<<<16, 64, 0, s2>>>();
    cudaEventRecord(e_ns, s2);

    // join: recur needs v (e_vog) + fact/iact/invden (e_ns)
    cudaStreamWaitEvent(0, e_ns, 0);
    cudaStreamWaitEvent(0, e_vog, 0);
    recur_kernel<<<dim3(8, 16), 256>>>();
    ln_gate_kernel<<<Bc * Sc, 256>>>(gamma);
    gemm_out_tc<<<dim3(8, 16), 128>>>(y);

    cudaEventDestroy(e1);
    cudaEventDestroy(e_cvt);
    cudaEventDestroy(e_qk);
    cudaEventDestroy(e_ns);
    cudaEventDestroy(e_vog);
    cudaStreamDestroy(s2);
    cudaStreamDestroy(s3);
}